// round 6
// baseline (speedup 1.0000x reference)
#include <cuda_runtime.h>
#include <cuda_bf16.h>
#include <cstdint>

#define N_FEATS 100000
#define B_ROWS  512
#define D_DIM   512
#define C_CLS   1854
#define TOPK    10

#define KC      32
#define NCH     (D_DIM / KC)
#define NSTAGE  3
#define STAGE_BYTES 32768
#define SMEM_TOTAL (NSTAGE * STAGE_BYTES)   // 96 KB -> 2 CTAs/SM
#define OFF_AH 0
#define OFF_AL 8192
#define OFF_BH 16384
#define OFF_BL 24576

#define SAMPLE_NT 16                 // sample = first 16*128 = 2048 columns
#define CAP 4096                     // per-row candidate capacity

__device__ float g_sim[(size_t)B_ROWS * N_FEATS];          // 204.8 MB
__device__ __nv_bfloat16 g_fhi[(size_t)N_FEATS * D_DIM];   // 102.4 MB
__device__ __nv_bfloat16 g_flo[(size_t)N_FEATS * D_DIM];   // 102.4 MB
__device__ __nv_bfloat16 g_ahi[B_ROWS * D_DIM];
__device__ __nv_bfloat16 g_alo[B_ROWS * D_DIM];
__device__ float g_thresh[B_ROWS];
__device__ int   g_ccnt[B_ROWS];
__device__ float g_cvv[(size_t)B_ROWS * CAP];              // 8 MB
__device__ int   g_cii[(size_t)B_ROWS * CAP];              // 8 MB
__device__ int   g_topk[B_ROWS * TOPK];

static __device__ __forceinline__ uint32_t smem_u32(const void* p) {
    uint32_t a;
    asm("{ .reg .u64 t; cvta.to.shared.u64 t, %1; cvt.u32.u64 %0, t; }" : "=r"(a) : "l"(p));
    return a;
}
static __device__ __forceinline__ void ldsm4(uint32_t (&r)[4], uint32_t addr) {
    asm volatile("ldmatrix.sync.aligned.m8n8.x4.shared.b16 {%0,%1,%2,%3}, [%4];"
                 : "=r"(r[0]), "=r"(r[1]), "=r"(r[2]), "=r"(r[3]) : "r"(addr));
}
static __device__ __forceinline__ void mma16816(float (&d)[4], const uint32_t (&a)[4],
                                                const uint32_t* b) {
    asm volatile(
        "mma.sync.aligned.m16n8k16.row.col.f32.bf16.bf16.f32 "
        "{%0,%1,%2,%3}, {%4,%5,%6,%7}, {%8,%9}, {%0,%1,%2,%3};"
        : "+f"(d[0]), "+f"(d[1]), "+f"(d[2]), "+f"(d[3])
        : "r"(a[0]), "r"(a[1]), "r"(a[2]), "r"(a[3]), "r"(b[0]), "r"(b[1]));
}
static __device__ __forceinline__ void cp16(uint32_t dst, const void* src, uint32_t sz) {
    asm volatile("cp.async.cg.shared.global [%0], [%1], 16, %2;"
                 :: "r"(dst), "l"(src), "r"(sz) : "memory");
}

// ---------------------------------------------------------------------------
// Pre-convert: fp32 -> (bf16 hi, bf16 lo)
// ---------------------------------------------------------------------------
__global__ void cvt_kernel(const float* __restrict__ src, __nv_bfloat16* __restrict__ hi,
                           __nv_bfloat16* __restrict__ lo, int n4) {
    int i = blockIdx.x * blockDim.x + threadIdx.x;
    if (i >= n4) return;
    float4 v = ((const float4*)src)[i];
    __nv_bfloat162 h01 = __floats2bfloat162_rn(v.x, v.y);
    __nv_bfloat162 h23 = __floats2bfloat162_rn(v.z, v.w);
    __nv_bfloat162 l01 = __floats2bfloat162_rn(v.x - __low2float(h01), v.y - __high2float(h01));
    __nv_bfloat162 l23 = __floats2bfloat162_rn(v.z - __low2float(h23), v.w - __high2float(h23));
    ((uint2*)hi)[i] = make_uint2(*(uint32_t*)&h01, *(uint32_t*)&h23);
    ((uint2*)lo)[i] = make_uint2(*(uint32_t*)&l01, *(uint32_t*)&l23);
}

__global__ void zero_cnt_kernel() {
    if (threadIdx.x < B_ROWS / 2)
        ((int2*)g_ccnt)[threadIdx.x + blockIdx.x * 0] = make_int2(0, 0);
}

// ---------------------------------------------------------------------------
// GEMM: cp.async 3-stage, split-bf16 HMMA (hh + hl + lh), optional fused filter
// ---------------------------------------------------------------------------
extern __shared__ char dsm[];

static __device__ __forceinline__ void issue_stage(uint32_t sbase, int c, int mg, int nt,
                                                   int tid) {
    const uint32_t stage = sbase + (c % NSTAGE) * STAGE_BYTES;
#pragma unroll
    for (int j = 0; j < 8; j++) {
        int id = tid + j * 256;
        int mat = id >> 9;          // 0:Ah 1:Al 2:Bh 3:Bl
        int rem = id & 511;
        int row = rem >> 2;
        int cc = rem & 3;
        uint32_t dst = stage + mat * 8192 + row * 64 + ((cc ^ ((row >> 1) & 3)) << 4);
        uint32_t sz = 16;
        const __nv_bfloat16* src;
        if (mat < 2) {
            src = (mat == 0 ? g_ahi : g_alo) + (size_t)(mg * 128 + row) * D_DIM + c * KC + cc * 8;
        } else {
            int n = nt * 128 + row;
            if (n >= N_FEATS) { sz = 0; n = 0; }
            src = (mat == 2 ? g_fhi : g_flo) + (size_t)n * D_DIM + c * KC + cc * 8;
        }
        cp16(dst, src, sz);
    }
    asm volatile("cp.async.commit_group;" ::: "memory");
}

static __device__ __forceinline__ void push_cand(int r, float v, int n) {
    int p = atomicAdd(&g_ccnt[r], 1);
    if (p < CAP) {
        g_cvv[(size_t)r * CAP + p] = v;
        g_cii[(size_t)r * CAP + p] = n;
    }
}

template <bool FILTER>
__global__ void __launch_bounds__(256, 2) gemm_hmma(void) {
    const int mg = blockIdx.x;
    const int nt = blockIdx.y;
    const int tid = threadIdx.x;
    const int lane = tid & 31, w = tid >> 5;
    const int wm = (w >> 2) * 64;
    const int wn = (w & 3) * 32;
    const uint32_t sb = smem_u32(dsm);

    float acc[4][4][4];
#pragma unroll
    for (int i = 0; i < 4; i++)
#pragma unroll
        for (int j = 0; j < 4; j++)
#pragma unroll
            for (int q = 0; q < 4; q++) acc[i][j][q] = 0.f;

    const int rA = wm + ((lane >> 3) & 1) * 8 + (lane & 7);
    const int a_c4 = lane >> 4;
    const int rB = wn + ((lane >> 4) & 1) * 8 + (lane & 7);
    const int b_c4 = (lane >> 3) & 1;

    uint32_t aAddr[4], bAddr[2];
    int rxA[4], rxB[2];
#pragma unroll
    for (int mf = 0; mf < 4; mf++) {
        int r = rA + mf * 16;
        aAddr[mf] = r * 64;
        rxA[mf] = (r >> 1) & 3;
    }
#pragma unroll
    for (int nf2 = 0; nf2 < 2; nf2++) {
        int r = rB + nf2 * 16;
        bAddr[nf2] = r * 64;
        rxB[nf2] = (r >> 1) & 3;
    }

    issue_stage(sb, 0, mg, nt, tid);
    issue_stage(sb, 1, mg, nt, tid);

#pragma unroll 1
    for (int c = 0; c < NCH; c++) {
        if (c < NCH - 2)
            asm volatile("cp.async.wait_group 1;" ::: "memory");
        else
            asm volatile("cp.async.wait_group 0;" ::: "memory");
        __syncthreads();
        if (c + 2 < NCH) issue_stage(sb, c + 2, mg, nt, tid);

        const uint32_t st = sb + (c % NSTAGE) * STAGE_BYTES;
#pragma unroll
        for (int kh = 0; kh < 2; kh++) {
            uint32_t Ah[4][4], Al[4][4], Bh[2][4], Bl[2][4];
#pragma unroll
            for (int mf = 0; mf < 4; mf++)
                ldsm4(Ah[mf], st + OFF_AH + aAddr[mf] + (((kh * 2 + a_c4) ^ rxA[mf]) << 4));
#pragma unroll
            for (int nf2 = 0; nf2 < 2; nf2++)
                ldsm4(Bh[nf2], st + OFF_BH + bAddr[nf2] + (((kh * 2 + b_c4) ^ rxB[nf2]) << 4));
#pragma unroll
            for (int mf = 0; mf < 4; mf++)
#pragma unroll
                for (int nf = 0; nf < 4; nf++)
                    mma16816(acc[mf][nf], Ah[mf], &Bh[nf >> 1][(nf & 1) * 2]);
#pragma unroll
            for (int nf2 = 0; nf2 < 2; nf2++)
                ldsm4(Bl[nf2], st + OFF_BL + bAddr[nf2] + (((kh * 2 + b_c4) ^ rxB[nf2]) << 4));
#pragma unroll
            for (int mf = 0; mf < 4; mf++)
#pragma unroll
                for (int nf = 0; nf < 4; nf++)
                    mma16816(acc[mf][nf], Ah[mf], &Bl[nf >> 1][(nf & 1) * 2]);
#pragma unroll
            for (int mf = 0; mf < 4; mf++)
                ldsm4(Al[mf], st + OFF_AL + aAddr[mf] + (((kh * 2 + a_c4) ^ rxA[mf]) << 4));
#pragma unroll
            for (int mf = 0; mf < 4; mf++)
#pragma unroll
                for (int nf = 0; nf < 4; nf++)
                    mma16816(acc[mf][nf], Al[mf], &Bh[nf >> 1][(nf & 1) * 2]);
        }
    }

    const int mrow = mg * 128 + wm + (lane >> 2);
    const int ncol = nt * 128 + wn + (lane & 3) * 2;
#pragma unroll
    for (int mf = 0; mf < 4; mf++) {
        const int r0 = mrow + mf * 16;
        const int r1 = r0 + 8;
        float th0, th1;
        if (FILTER) { th0 = g_thresh[r0]; th1 = g_thresh[r1]; }
#pragma unroll
        for (int nf = 0; nf < 4; nf++) {
            int n = ncol + nf * 8;
            if (n < N_FEATS) {
                *(float2*)(g_sim + (size_t)r0 * N_FEATS + n) =
                    make_float2(acc[mf][nf][0], acc[mf][nf][1]);
                *(float2*)(g_sim + (size_t)r1 * N_FEATS + n) =
                    make_float2(acc[mf][nf][2], acc[mf][nf][3]);
                if (FILTER) {
                    if (acc[mf][nf][0] >= th0) push_cand(r0, acc[mf][nf][0], n);
                    if (acc[mf][nf][1] >= th0) push_cand(r0, acc[mf][nf][1], n + 1);
                    if (acc[mf][nf][2] >= th1) push_cand(r1, acc[mf][nf][2], n);
                    if (acc[mf][nf][3] >= th1) push_cand(r1, acc[mf][nf][3], n + 1);
                }
            }
        }
    }
}

// ---------------------------------------------------------------------------
// Top-10 machinery (tie-break: lower index, matching stable argsort)
// ---------------------------------------------------------------------------
static __device__ __forceinline__ bool better(float v, int j, float v2, int j2) {
    return v > v2 || (v == v2 && j < j2);
}
static __device__ __forceinline__ void insert10(float (&tv)[TOPK], int (&ti)[TOPK],
                                                float v, int j) {
    if (!better(v, j, tv[TOPK - 1], ti[TOPK - 1])) return;
    bool b[TOPK];
#pragma unroll
    for (int p = 0; p < TOPK; p++) b[p] = better(v, j, tv[p], ti[p]);
#pragma unroll
    for (int p = TOPK - 1; p >= 1; p--) {
        if (b[p]) {
            if (b[p - 1]) { tv[p] = tv[p - 1]; ti[p] = ti[p - 1]; }
            else          { tv[p] = v;         ti[p] = j;         }
        }
    }
    if (b[0]) { tv[0] = v; ti[0] = j; }
}

#define TK_THREADS 256

// Two-stage block merge of per-thread top-10s; returns final via sv2/si2 in thread 0.
static __device__ __forceinline__ void block_merge10(float (&tv)[TOPK], int (&ti)[TOPK],
                                                     float* sv, int* si, float* sv2,
                                                     int* si2, int tid) {
#pragma unroll
    for (int p = 0; p < TOPK; p++) { sv[tid * TOPK + p] = tv[p]; si[tid * TOPK + p] = ti[p]; }
    __syncthreads();
    if (tid < 32) {
#pragma unroll
        for (int p = 0; p < TOPK; p++) { tv[p] = -__int_as_float(0x7f800000); ti[p] = 0x7fffffff; }
        for (int c = tid * 80; c < (tid + 1) * 80; c++)
            insert10(tv, ti, sv[c], si[c]);
#pragma unroll
        for (int p = 0; p < TOPK; p++) { sv2[tid * TOPK + p] = tv[p]; si2[tid * TOPK + p] = ti[p]; }
    }
    __syncthreads();
    if (tid == 0) {
#pragma unroll
        for (int p = 0; p < TOPK; p++) { tv[p] = -__int_as_float(0x7f800000); ti[p] = 0x7fffffff; }
        for (int c = 0; c < 32 * TOPK; c++)
            insert10(tv, ti, sv2[c], si2[c]);
    }
}

// Threshold: exact 10th-largest of row's first SAMPLE_NT*128 sims
__global__ void __launch_bounds__(TK_THREADS) thresh_kernel() {
    const int row = blockIdx.x;
    const float* s = g_sim + (size_t)row * N_FEATS;
    const int tid = threadIdx.x;
    __shared__ float sv[TK_THREADS * TOPK];
    __shared__ int   si[TK_THREADS * TOPK];
    __shared__ float sv2[32 * TOPK];
    __shared__ int   si2[32 * TOPK];

    float tv[TOPK]; int ti[TOPK];
#pragma unroll
    for (int p = 0; p < TOPK; p++) { tv[p] = -__int_as_float(0x7f800000); ti[p] = 0x7fffffff; }
    for (int j = tid; j < SAMPLE_NT * 128; j += TK_THREADS)
        insert10(tv, ti, s[j], j);
    block_merge10(tv, ti, sv, si, sv2, si2, tid);
    if (tid == 0) g_thresh[row] = tv[TOPK - 1];
}

// Select: exact top-10 from candidate list (fallback: full row scan)
__global__ void __launch_bounds__(TK_THREADS) select_kernel() {
    const int row = blockIdx.x;
    const int tid = threadIdx.x;
    __shared__ float sv[TK_THREADS * TOPK];
    __shared__ int   si[TK_THREADS * TOPK];
    __shared__ float sv2[32 * TOPK];
    __shared__ int   si2[32 * TOPK];

    float tv[TOPK]; int ti[TOPK];
#pragma unroll
    for (int p = 0; p < TOPK; p++) { tv[p] = -__int_as_float(0x7f800000); ti[p] = 0x7fffffff; }

    const int cnt = g_ccnt[row];
    if (cnt <= CAP) {
        const float* cv = g_cvv + (size_t)row * CAP;
        const int*   ci = g_cii + (size_t)row * CAP;
        for (int c = tid; c < cnt; c += TK_THREADS)
            insert10(tv, ti, cv[c], ci[c]);
    } else {
        const float* s = g_sim + (size_t)row * N_FEATS;
        for (int j = tid; j < N_FEATS; j += TK_THREADS)
            insert10(tv, ti, s[j], j);
    }
    block_merge10(tv, ti, sv, si, sv2, si2, tid);
    if (tid == 0) {
#pragma unroll
        for (int p = 0; p < TOPK; p++) g_topk[row * TOPK + p] = ti[p];
    }
}

// ---------------------------------------------------------------------------
__global__ void zero_kernel(float4* __restrict__ out, int n4) {
    int i = blockIdx.x * blockDim.x + threadIdx.x;
    if (i < n4) out[i] = make_float4(0.f, 0.f, 0.f, 0.f);
}
__global__ void scatter_kernel(const int* __restrict__ y, float* __restrict__ out) {
    int row = blockIdx.x;
    int t = threadIdx.x;
    if (t < TOPK) {
        int idx = g_topk[row * TOPK + t];
        int cls = y[idx];
        out[(size_t)row * C_CLS + cls] = 1.0f;
    }
}

// ---------------------------------------------------------------------------
extern "C" void kernel_launch(void* const* d_in, const int* in_sizes, int n_in,
                              void* d_out, int out_size) {
    const float* y_pred = (const float*)d_in[0];
    const float* feats  = (const float*)d_in[1];
    const int*   y      = (const int*)d_in[2];
    float* out = (float*)d_out;

    static __nv_bfloat16 *p_fhi = nullptr, *p_flo = nullptr, *p_ahi = nullptr, *p_alo = nullptr;
    if (!p_fhi) {
        cudaGetSymbolAddress((void**)&p_fhi, g_fhi);
        cudaGetSymbolAddress((void**)&p_flo, g_flo);
        cudaGetSymbolAddress((void**)&p_ahi, g_ahi);
        cudaGetSymbolAddress((void**)&p_alo, g_alo);
        cudaFuncSetAttribute(gemm_hmma<false>, cudaFuncAttributeMaxDynamicSharedMemorySize,
                             SMEM_TOTAL);
        cudaFuncSetAttribute(gemm_hmma<true>, cudaFuncAttributeMaxDynamicSharedMemorySize,
                             SMEM_TOTAL);
    }

    cvt_kernel<<<(N_FEATS * D_DIM / 4 + 255) / 256, 256>>>(feats, p_fhi, p_flo,
                                                           N_FEATS * D_DIM / 4);
    cvt_kernel<<<(B_ROWS * D_DIM / 4 + 255) / 256, 256>>>(y_pred, p_ahi, p_alo,
                                                          B_ROWS * D_DIM / 4);
    zero_cnt_kernel<<<1, 256>>>();

    // Sample GEMM: first 2048 columns only
    gemm_hmma<false><<<dim3(4, SAMPLE_NT), 256, SMEM_TOTAL>>>();
    thresh_kernel<<<B_ROWS, TK_THREADS>>>();

    // Main GEMM with fused candidate filter
    gemm_hmma<true><<<dim3(4, (N_FEATS + 127) / 128), 256, SMEM_TOTAL>>>();

    select_kernel<<<B_ROWS, TK_THREADS>>>();

    int n4 = out_size / 4;
    zero_kernel<<<(n4 + 255) / 256, 256>>>((float4*)out, n4);
    scatter_kernel<<<B_ROWS, 32>>>(y, out);
}

// round 7
// speedup vs baseline: 1.0292x; 1.0292x over previous
#include <cuda_runtime.h>
#include <cuda_bf16.h>
#include <cstdint>

#define N_FEATS 100000
#define B_ROWS  512
#define D_DIM   512
#define C_CLS   1854
#define TOPK    10

#define KC      32
#define NCH     (D_DIM / KC)
#define NSTAGE  3
#define STAGE_BYTES 32768
#define SMEM_TOTAL (NSTAGE * STAGE_BYTES)   // 96 KB -> 2 CTAs/SM
#define OFF_AH 0
#define OFF_AL 8192
#define OFF_BH 16384
#define OFF_BL 24576

#define SAMPLE_NT 16                 // sample = first 16*128 = 2048 columns
#define SAMPLE_COLS (SAMPLE_NT * 128)
#define CAP 4096                     // per-row candidate capacity

__device__ __nv_bfloat16 g_fhi[(size_t)N_FEATS * D_DIM];   // 102.4 MB
__device__ __nv_bfloat16 g_flo[(size_t)N_FEATS * D_DIM];   // 102.4 MB
__device__ __nv_bfloat16 g_ahi[B_ROWS * D_DIM];
__device__ __nv_bfloat16 g_alo[B_ROWS * D_DIM];
__device__ float g_sample[(size_t)B_ROWS * SAMPLE_COLS];   // 4 MB
__device__ float g_thresh[B_ROWS];
__device__ int   g_ccnt[B_ROWS];
__device__ float g_cvv[(size_t)B_ROWS * CAP];              // 8 MB
__device__ int   g_cii[(size_t)B_ROWS * CAP];              // 8 MB
__device__ int   g_topk[B_ROWS * TOPK];

static __device__ __forceinline__ uint32_t smem_u32(const void* p) {
    uint32_t a;
    asm("{ .reg .u64 t; cvta.to.shared.u64 t, %1; cvt.u32.u64 %0, t; }" : "=r"(a) : "l"(p));
    return a;
}
static __device__ __forceinline__ void ldsm4(uint32_t (&r)[4], uint32_t addr) {
    asm volatile("ldmatrix.sync.aligned.m8n8.x4.shared.b16 {%0,%1,%2,%3}, [%4];"
                 : "=r"(r[0]), "=r"(r[1]), "=r"(r[2]), "=r"(r[3]) : "r"(addr));
}
static __device__ __forceinline__ void mma16816(float (&d)[4], const uint32_t (&a)[4],
                                                const uint32_t* b) {
    asm volatile(
        "mma.sync.aligned.m16n8k16.row.col.f32.bf16.bf16.f32 "
        "{%0,%1,%2,%3}, {%4,%5,%6,%7}, {%8,%9}, {%0,%1,%2,%3};"
        : "+f"(d[0]), "+f"(d[1]), "+f"(d[2]), "+f"(d[3])
        : "r"(a[0]), "r"(a[1]), "r"(a[2]), "r"(a[3]), "r"(b[0]), "r"(b[1]));
}
static __device__ __forceinline__ void cp16(uint32_t dst, const void* src, uint32_t sz) {
    asm volatile("cp.async.cg.shared.global [%0], [%1], 16, %2;"
                 :: "r"(dst), "l"(src), "r"(sz) : "memory");
}

// ---------------------------------------------------------------------------
// Pre-convert: fp32 -> (bf16 hi, bf16 lo)
// ---------------------------------------------------------------------------
__global__ void cvt_kernel(const float* __restrict__ src, __nv_bfloat16* __restrict__ hi,
                           __nv_bfloat16* __restrict__ lo, int n4) {
    int i = blockIdx.x * blockDim.x + threadIdx.x;
    if (i >= n4) return;
    float4 v = ((const float4*)src)[i];
    __nv_bfloat162 h01 = __floats2bfloat162_rn(v.x, v.y);
    __nv_bfloat162 h23 = __floats2bfloat162_rn(v.z, v.w);
    __nv_bfloat162 l01 = __floats2bfloat162_rn(v.x - __low2float(h01), v.y - __high2float(h01));
    __nv_bfloat162 l23 = __floats2bfloat162_rn(v.z - __low2float(h23), v.w - __high2float(h23));
    ((uint2*)hi)[i] = make_uint2(*(uint32_t*)&h01, *(uint32_t*)&h23);
    ((uint2*)lo)[i] = make_uint2(*(uint32_t*)&l01, *(uint32_t*)&l23);
}

__global__ void zero_cnt_kernel() {
    ((int2*)g_ccnt)[threadIdx.x] = make_int2(0, 0);   // 256 threads x int2 = 512
}

// ---------------------------------------------------------------------------
// GEMM: cp.async 3-stage, split-bf16 HMMA (hh + hl + lh)
// MODE 0: store sims to g_sample (sample pass, nt < SAMPLE_NT)
// MODE 1: no stores; push candidates >= per-row threshold
// ---------------------------------------------------------------------------
extern __shared__ char dsm[];

static __device__ __forceinline__ void issue_stage(uint32_t sbase, int c, int mg, int nt,
                                                   int tid) {
    const uint32_t stage = sbase + (c % NSTAGE) * STAGE_BYTES;
#pragma unroll
    for (int j = 0; j < 8; j++) {
        int id = tid + j * 256;
        int mat = id >> 9;          // 0:Ah 1:Al 2:Bh 3:Bl
        int rem = id & 511;
        int row = rem >> 2;
        int cc = rem & 3;
        uint32_t dst = stage + mat * 8192 + row * 64 + ((cc ^ ((row >> 1) & 3)) << 4);
        uint32_t sz = 16;
        const __nv_bfloat16* src;
        if (mat < 2) {
            src = (mat == 0 ? g_ahi : g_alo) + (size_t)(mg * 128 + row) * D_DIM + c * KC + cc * 8;
        } else {
            int n = nt * 128 + row;
            if (n >= N_FEATS) { sz = 0; n = 0; }
            src = (mat == 2 ? g_fhi : g_flo) + (size_t)n * D_DIM + c * KC + cc * 8;
        }
        cp16(dst, src, sz);
    }
    asm volatile("cp.async.commit_group;" ::: "memory");
}

static __device__ __forceinline__ void push_cand(int r, float v, int n) {
    int p = atomicAdd(&g_ccnt[r], 1);
    if (p < CAP) {
        g_cvv[(size_t)r * CAP + p] = v;
        g_cii[(size_t)r * CAP + p] = n;
    }
}

template <int MODE>
__global__ void __launch_bounds__(256, 2) gemm_hmma(void) {
    const int mg = blockIdx.x;
    const int nt = blockIdx.y;
    const int tid = threadIdx.x;
    const int lane = tid & 31, w = tid >> 5;
    const int wm = (w >> 2) * 64;
    const int wn = (w & 3) * 32;
    const uint32_t sb = smem_u32(dsm);

    float acc[4][4][4];
#pragma unroll
    for (int i = 0; i < 4; i++)
#pragma unroll
        for (int j = 0; j < 4; j++)
#pragma unroll
            for (int q = 0; q < 4; q++) acc[i][j][q] = 0.f;

    const int rA = wm + ((lane >> 3) & 1) * 8 + (lane & 7);
    const int a_c4 = lane >> 4;
    const int rB = wn + ((lane >> 4) & 1) * 8 + (lane & 7);
    const int b_c4 = (lane >> 3) & 1;

    uint32_t aAddr[4], bAddr[2];
    int rxA[4], rxB[2];
#pragma unroll
    for (int mf = 0; mf < 4; mf++) {
        int r = rA + mf * 16;
        aAddr[mf] = r * 64;
        rxA[mf] = (r >> 1) & 3;
    }
#pragma unroll
    for (int nf2 = 0; nf2 < 2; nf2++) {
        int r = rB + nf2 * 16;
        bAddr[nf2] = r * 64;
        rxB[nf2] = (r >> 1) & 3;
    }

    issue_stage(sb, 0, mg, nt, tid);
    issue_stage(sb, 1, mg, nt, tid);

#pragma unroll 1
    for (int c = 0; c < NCH; c++) {
        if (c < NCH - 2)
            asm volatile("cp.async.wait_group 1;" ::: "memory");
        else
            asm volatile("cp.async.wait_group 0;" ::: "memory");
        __syncthreads();
        if (c + 2 < NCH) issue_stage(sb, c + 2, mg, nt, tid);

        const uint32_t st = sb + (c % NSTAGE) * STAGE_BYTES;
#pragma unroll
        for (int kh = 0; kh < 2; kh++) {
            uint32_t Ah[4][4], Al[4][4], Bh[2][4], Bl[2][4];
#pragma unroll
            for (int mf = 0; mf < 4; mf++)
                ldsm4(Ah[mf], st + OFF_AH + aAddr[mf] + (((kh * 2 + a_c4) ^ rxA[mf]) << 4));
#pragma unroll
            for (int nf2 = 0; nf2 < 2; nf2++)
                ldsm4(Bh[nf2], st + OFF_BH + bAddr[nf2] + (((kh * 2 + b_c4) ^ rxB[nf2]) << 4));
#pragma unroll
            for (int mf = 0; mf < 4; mf++)
#pragma unroll
                for (int nf = 0; nf < 4; nf++)
                    mma16816(acc[mf][nf], Ah[mf], &Bh[nf >> 1][(nf & 1) * 2]);
#pragma unroll
            for (int nf2 = 0; nf2 < 2; nf2++)
                ldsm4(Bl[nf2], st + OFF_BL + bAddr[nf2] + (((kh * 2 + b_c4) ^ rxB[nf2]) << 4));
#pragma unroll
            for (int mf = 0; mf < 4; mf++)
#pragma unroll
                for (int nf = 0; nf < 4; nf++)
                    mma16816(acc[mf][nf], Ah[mf], &Bl[nf >> 1][(nf & 1) * 2]);
#pragma unroll
            for (int mf = 0; mf < 4; mf++)
                ldsm4(Al[mf], st + OFF_AL + aAddr[mf] + (((kh * 2 + a_c4) ^ rxA[mf]) << 4));
#pragma unroll
            for (int mf = 0; mf < 4; mf++)
#pragma unroll
                for (int nf = 0; nf < 4; nf++)
                    mma16816(acc[mf][nf], Al[mf], &Bh[nf >> 1][(nf & 1) * 2]);
        }
    }

    const int mrow = mg * 128 + wm + (lane >> 2);
    const int ncol = nt * 128 + wn + (lane & 3) * 2;

    if (MODE == 0) {
        // Sample pass: store sims to g_sample (row stride SAMPLE_COLS)
#pragma unroll
        for (int mf = 0; mf < 4; mf++) {
#pragma unroll
            for (int nf = 0; nf < 4; nf++) {
                int n = ncol + nf * 8;
                size_t r0 = (size_t)(mrow + mf * 16);
                *(float2*)(g_sample + r0 * SAMPLE_COLS + n) =
                    make_float2(acc[mf][nf][0], acc[mf][nf][1]);
                *(float2*)(g_sample + (r0 + 8) * SAMPLE_COLS + n) =
                    make_float2(acc[mf][nf][2], acc[mf][nf][3]);
            }
        }
    } else {
        // Filter pass: push candidates only
#pragma unroll
        for (int mf = 0; mf < 4; mf++) {
            const int r0 = mrow + mf * 16;
            const int r1 = r0 + 8;
            const float th0 = g_thresh[r0];
            const float th1 = g_thresh[r1];
#pragma unroll
            for (int nf = 0; nf < 4; nf++) {
                int n = ncol + nf * 8;
                if (n < N_FEATS) {
                    if (acc[mf][nf][0] >= th0) push_cand(r0, acc[mf][nf][0], n);
                    if (acc[mf][nf][1] >= th0) push_cand(r0, acc[mf][nf][1], n + 1);
                    if (acc[mf][nf][2] >= th1) push_cand(r1, acc[mf][nf][2], n);
                    if (acc[mf][nf][3] >= th1) push_cand(r1, acc[mf][nf][3], n + 1);
                }
            }
        }
    }
}

// ---------------------------------------------------------------------------
// Top-10 machinery (tie-break: lower index, matching stable argsort)
// ---------------------------------------------------------------------------
static __device__ __forceinline__ bool better(float v, int j, float v2, int j2) {
    return v > v2 || (v == v2 && j < j2);
}
static __device__ __forceinline__ void insert10(float (&tv)[TOPK], int (&ti)[TOPK],
                                                float v, int j) {
    if (!better(v, j, tv[TOPK - 1], ti[TOPK - 1])) return;
    bool b[TOPK];
#pragma unroll
    for (int p = 0; p < TOPK; p++) b[p] = better(v, j, tv[p], ti[p]);
#pragma unroll
    for (int p = TOPK - 1; p >= 1; p--) {
        if (b[p]) {
            if (b[p - 1]) { tv[p] = tv[p - 1]; ti[p] = ti[p - 1]; }
            else          { tv[p] = v;         ti[p] = j;         }
        }
    }
    if (b[0]) { tv[0] = v; ti[0] = j; }
}

#define TK_THREADS 256

static __device__ __forceinline__ void block_merge10(float (&tv)[TOPK], int (&ti)[TOPK],
                                                     float* sv, int* si, float* sv2,
                                                     int* si2, int tid) {
#pragma unroll
    for (int p = 0; p < TOPK; p++) { sv[tid * TOPK + p] = tv[p]; si[tid * TOPK + p] = ti[p]; }
    __syncthreads();
    if (tid < 32) {
#pragma unroll
        for (int p = 0; p < TOPK; p++) { tv[p] = -__int_as_float(0x7f800000); ti[p] = 0x7fffffff; }
        for (int c = tid * 80; c < (tid + 1) * 80; c++)
            insert10(tv, ti, sv[c], si[c]);
#pragma unroll
        for (int p = 0; p < TOPK; p++) { sv2[tid * TOPK + p] = tv[p]; si2[tid * TOPK + p] = ti[p]; }
    }
    __syncthreads();
    if (tid == 0) {
#pragma unroll
        for (int p = 0; p < TOPK; p++) { tv[p] = -__int_as_float(0x7f800000); ti[p] = 0x7fffffff; }
        for (int c = 0; c < 32 * TOPK; c++)
            insert10(tv, ti, sv2[c], si2[c]);
    }
}

// Threshold: exact 10th-largest of row's sample sims
__global__ void __launch_bounds__(TK_THREADS) thresh_kernel() {
    const int row = blockIdx.x;
    const float* s = g_sample + (size_t)row * SAMPLE_COLS;
    const int tid = threadIdx.x;
    __shared__ float sv[TK_THREADS * TOPK];
    __shared__ int   si[TK_THREADS * TOPK];
    __shared__ float sv2[32 * TOPK];
    __shared__ int   si2[32 * TOPK];

    float tv[TOPK]; int ti[TOPK];
#pragma unroll
    for (int p = 0; p < TOPK; p++) { tv[p] = -__int_as_float(0x7f800000); ti[p] = 0x7fffffff; }
    for (int j = tid; j < SAMPLE_COLS; j += TK_THREADS)
        insert10(tv, ti, s[j], j);
    block_merge10(tv, ti, sv, si, sv2, si2, tid);
    if (tid == 0) g_thresh[row] = tv[TOPK - 1];
}

// Select: exact top-10 from candidate list (overflow rows handled by fallback)
__global__ void __launch_bounds__(TK_THREADS) select_kernel() {
    const int row = blockIdx.x;
    const int tid = threadIdx.x;
    const int cnt = g_ccnt[row];
    if (cnt > CAP) return;

    __shared__ float sv[TK_THREADS * TOPK];
    __shared__ int   si[TK_THREADS * TOPK];
    __shared__ float sv2[32 * TOPK];
    __shared__ int   si2[32 * TOPK];

    float tv[TOPK]; int ti[TOPK];
#pragma unroll
    for (int p = 0; p < TOPK; p++) { tv[p] = -__int_as_float(0x7f800000); ti[p] = 0x7fffffff; }
    const float* cv = g_cvv + (size_t)row * CAP;
    const int*   ci = g_cii + (size_t)row * CAP;
    for (int c = tid; c < cnt; c += TK_THREADS)
        insert10(tv, ti, cv[c], ci[c]);
    block_merge10(tv, ti, sv, si, sv2, si2, tid);
    if (tid == 0) {
#pragma unroll
        for (int p = 0; p < TOPK; p++) g_topk[row * TOPK + p] = ti[p];
    }
}

// Fallback: brute-force exact fp32 top-10 for overflow rows (normally a no-op)
__global__ void __launch_bounds__(TK_THREADS) fallback_kernel(const float* __restrict__ yp,
                                                              const float* __restrict__ feats) {
    const int row = blockIdx.x;
    if (g_ccnt[row] <= CAP) return;
    const int tid = threadIdx.x;

    __shared__ float4 a4[D_DIM / 4];
    __shared__ float sv[TK_THREADS * TOPK];
    __shared__ int   si[TK_THREADS * TOPK];
    __shared__ float sv2[32 * TOPK];
    __shared__ int   si2[32 * TOPK];

    if (tid < D_DIM / 4) a4[tid] = ((const float4*)(yp + (size_t)row * D_DIM))[tid];
    __syncthreads();

    float tv[TOPK]; int ti[TOPK];
#pragma unroll
    for (int p = 0; p < TOPK; p++) { tv[p] = -__int_as_float(0x7f800000); ti[p] = 0x7fffffff; }
    for (int col = tid; col < N_FEATS; col += TK_THREADS) {
        const float4* f4 = (const float4*)(feats + (size_t)col * D_DIM);
        float s = 0.f;
#pragma unroll 8
        for (int q = 0; q < D_DIM / 4; q++) {
            float4 b = f4[q], a = a4[q];
            s += a.x * b.x + a.y * b.y + a.z * b.z + a.w * b.w;
        }
        insert10(tv, ti, s, col);
    }
    block_merge10(tv, ti, sv, si, sv2, si2, tid);
    if (tid == 0) {
#pragma unroll
        for (int p = 0; p < TOPK; p++) g_topk[row * TOPK + p] = ti[p];
    }
}

// ---------------------------------------------------------------------------
__global__ void zero_kernel(float4* __restrict__ out, int n4) {
    int i = blockIdx.x * blockDim.x + threadIdx.x;
    if (i < n4) out[i] = make_float4(0.f, 0.f, 0.f, 0.f);
}
__global__ void scatter_kernel(const int* __restrict__ y, float* __restrict__ out) {
    int row = blockIdx.x;
    int t = threadIdx.x;
    if (t < TOPK) {
        int idx = g_topk[row * TOPK + t];
        int cls = y[idx];
        out[(size_t)row * C_CLS + cls] = 1.0f;
    }
}

// ---------------------------------------------------------------------------
extern "C" void kernel_launch(void* const* d_in, const int* in_sizes, int n_in,
                              void* d_out, int out_size) {
    const float* y_pred = (const float*)d_in[0];
    const float* feats  = (const float*)d_in[1];
    const int*   y      = (const int*)d_in[2];
    float* out = (float*)d_out;

    static __nv_bfloat16 *p_fhi = nullptr, *p_flo = nullptr, *p_ahi = nullptr, *p_alo = nullptr;
    if (!p_fhi) {
        cudaGetSymbolAddress((void**)&p_fhi, g_fhi);
        cudaGetSymbolAddress((void**)&p_flo, g_flo);
        cudaGetSymbolAddress((void**)&p_ahi, g_ahi);
        cudaGetSymbolAddress((void**)&p_alo, g_alo);
        cudaFuncSetAttribute(gemm_hmma<0>, cudaFuncAttributeMaxDynamicSharedMemorySize,
                             SMEM_TOTAL);
        cudaFuncSetAttribute(gemm_hmma<1>, cudaFuncAttributeMaxDynamicSharedMemorySize,
                             SMEM_TOTAL);
    }

    cvt_kernel<<<(N_FEATS * D_DIM / 4 + 255) / 256, 256>>>(feats, p_fhi, p_flo,
                                                           N_FEATS * D_DIM / 4);
    cvt_kernel<<<(B_ROWS * D_DIM / 4 + 255) / 256, 256>>>(y_pred, p_ahi, p_alo,
                                                          B_ROWS * D_DIM / 4);
    zero_cnt_kernel<<<1, 256>>>();

    // Sample GEMM: first 2048 columns -> g_sample
    gemm_hmma<0><<<dim3(4, SAMPLE_NT), 256, SMEM_TOTAL>>>();
    thresh_kernel<<<B_ROWS, TK_THREADS>>>();

    // Main GEMM: fused candidate filter, no sim stores
    gemm_hmma<1><<<dim3(4, (N_FEATS + 127) / 128), 256, SMEM_TOTAL>>>();

    select_kernel<<<B_ROWS, TK_THREADS>>>();
    fallback_kernel<<<B_ROWS, TK_THREADS>>>(y_pred, feats);

    int n4 = out_size / 4;
    zero_kernel<<<(n4 + 255) / 256, 256>>>((float4*)out, n4);
    scatter_kernel<<<B_ROWS, 32>>>(y, out);
}

// round 8
// speedup vs baseline: 1.0329x; 1.0036x over previous
#include <cuda_runtime.h>
#include <cuda_bf16.h>
#include <cstdint>

#define N_FEATS 100000
#define B_ROWS  512
#define D_DIM   512
#define C_CLS   1854
#define TOPK    10

#define KC      32
#define NCH     (D_DIM / KC)
#define NSTAGE  3
#define STAGE_BYTES 32768
#define SMEM_TOTAL 98304            // 96 KB: 3-stage pipeline, reused by epilogue staging
#define OFF_AH 0
#define OFF_AL 8192
#define OFF_BH 16384
#define OFF_BL 24576

#define EPI_STRIDE 132              // floats per row in epilogue smem staging

#define SAMPLE_NT 16                // sample = first 2048 columns
#define SAMPLE_COLS (SAMPLE_NT * 128)
#define CAP 4096

__device__ __nv_bfloat16 g_fhi[(size_t)N_FEATS * D_DIM];
__device__ __nv_bfloat16 g_flo[(size_t)N_FEATS * D_DIM];
__device__ __nv_bfloat16 g_ahi[B_ROWS * D_DIM];
__device__ __nv_bfloat16 g_alo[B_ROWS * D_DIM];
__device__ float g_sample[(size_t)B_ROWS * SAMPLE_COLS];
__device__ float g_thresh[B_ROWS];
__device__ int   g_ccnt[B_ROWS];
__device__ float g_cvv[(size_t)B_ROWS * CAP];
__device__ int   g_cii[(size_t)B_ROWS * CAP];
__device__ int   g_topk[B_ROWS * TOPK];

static __device__ __forceinline__ uint32_t smem_u32(const void* p) {
    uint32_t a;
    asm("{ .reg .u64 t; cvta.to.shared.u64 t, %1; cvt.u32.u64 %0, t; }" : "=r"(a) : "l"(p));
    return a;
}
static __device__ __forceinline__ void ldsm4(uint32_t (&r)[4], uint32_t addr) {
    asm volatile("ldmatrix.sync.aligned.m8n8.x4.shared.b16 {%0,%1,%2,%3}, [%4];"
                 : "=r"(r[0]), "=r"(r[1]), "=r"(r[2]), "=r"(r[3]) : "r"(addr));
}
static __device__ __forceinline__ void mma16816(float (&d)[4], const uint32_t (&a)[4],
                                                const uint32_t* b) {
    asm volatile(
        "mma.sync.aligned.m16n8k16.row.col.f32.bf16.bf16.f32 "
        "{%0,%1,%2,%3}, {%4,%5,%6,%7}, {%8,%9}, {%0,%1,%2,%3};"
        : "+f"(d[0]), "+f"(d[1]), "+f"(d[2]), "+f"(d[3])
        : "r"(a[0]), "r"(a[1]), "r"(a[2]), "r"(a[3]), "r"(b[0]), "r"(b[1]));
}
static __device__ __forceinline__ void cp16(uint32_t dst, const void* src, uint32_t sz) {
    asm volatile("cp.async.cg.shared.global [%0], [%1], 16, %2;"
                 :: "r"(dst), "l"(src), "r"(sz) : "memory");
}

// ---------------------------------------------------------------------------
// Pre-convert: fp32 -> (bf16 hi, bf16 lo), 32B per thread
// ---------------------------------------------------------------------------
__global__ void cvt_kernel(const float* __restrict__ src, __nv_bfloat16* __restrict__ hi,
                           __nv_bfloat16* __restrict__ lo, int n8) {
    int i = blockIdx.x * blockDim.x + threadIdx.x;
    if (i >= n8) return;
    float4 v0 = ((const float4*)src)[i * 2];
    float4 v1 = ((const float4*)src)[i * 2 + 1];
    __nv_bfloat162 h0 = __floats2bfloat162_rn(v0.x, v0.y);
    __nv_bfloat162 h1 = __floats2bfloat162_rn(v0.z, v0.w);
    __nv_bfloat162 h2 = __floats2bfloat162_rn(v1.x, v1.y);
    __nv_bfloat162 h3 = __floats2bfloat162_rn(v1.z, v1.w);
    __nv_bfloat162 l0 = __floats2bfloat162_rn(v0.x - __low2float(h0), v0.y - __high2float(h0));
    __nv_bfloat162 l1 = __floats2bfloat162_rn(v0.z - __low2float(h1), v0.w - __high2float(h1));
    __nv_bfloat162 l2 = __floats2bfloat162_rn(v1.x - __low2float(h2), v1.y - __high2float(h2));
    __nv_bfloat162 l3 = __floats2bfloat162_rn(v1.z - __low2float(h3), v1.w - __high2float(h3));
    ((uint4*)hi)[i] = make_uint4(*(uint32_t*)&h0, *(uint32_t*)&h1,
                                 *(uint32_t*)&h2, *(uint32_t*)&h3);
    ((uint4*)lo)[i] = make_uint4(*(uint32_t*)&l0, *(uint32_t*)&l1,
                                 *(uint32_t*)&l2, *(uint32_t*)&l3);
}

__global__ void zero_cnt_kernel() {
    ((int2*)g_ccnt)[threadIdx.x] = make_int2(0, 0);
}

// ---------------------------------------------------------------------------
// GEMM: cp.async 3-stage, split-bf16 HMMA (hh + hl + lh)
// MODE 0: store sims to g_sample   MODE 1: smem-staged filter, push candidates
// ---------------------------------------------------------------------------
extern __shared__ char dsm[];

static __device__ __forceinline__ void issue_stage(uint32_t sbase, int c, int mg, int nt,
                                                   int tid) {
    const uint32_t stage = sbase + (c % NSTAGE) * STAGE_BYTES;
#pragma unroll
    for (int j = 0; j < 8; j++) {
        int id = tid + j * 256;
        int mat = id >> 9;
        int rem = id & 511;
        int row = rem >> 2;
        int cc = rem & 3;
        uint32_t dst = stage + mat * 8192 + row * 64 + ((cc ^ ((row >> 1) & 3)) << 4);
        uint32_t sz = 16;
        const __nv_bfloat16* src;
        if (mat < 2) {
            src = (mat == 0 ? g_ahi : g_alo) + (size_t)(mg * 128 + row) * D_DIM + c * KC + cc * 8;
        } else {
            int n = nt * 128 + row;
            if (n >= N_FEATS) { sz = 0; n = 0; }
            src = (mat == 2 ? g_fhi : g_flo) + (size_t)n * D_DIM + c * KC + cc * 8;
        }
        cp16(dst, src, sz);
    }
    asm volatile("cp.async.commit_group;" ::: "memory");
}

template <int MODE>
__global__ void __launch_bounds__(256, 2) gemm_hmma(void) {
    const int mg = blockIdx.x;
    const int nt = blockIdx.y;
    const int tid = threadIdx.x;
    const int lane = tid & 31, w = tid >> 5;
    const int wm = (w >> 2) * 64;
    const int wn = (w & 3) * 32;
    const uint32_t sb = smem_u32(dsm);

    float acc[4][4][4];
#pragma unroll
    for (int i = 0; i < 4; i++)
#pragma unroll
        for (int j = 0; j < 4; j++)
#pragma unroll
            for (int q = 0; q < 4; q++) acc[i][j][q] = 0.f;

    const int rA = wm + ((lane >> 3) & 1) * 8 + (lane & 7);
    const int a_c4 = lane >> 4;
    const int rB = wn + ((lane >> 4) & 1) * 8 + (lane & 7);
    const int b_c4 = (lane >> 3) & 1;

    uint32_t aAddr[4], bAddr[2];
    int rxA[4], rxB[2];
#pragma unroll
    for (int mf = 0; mf < 4; mf++) {
        int r = rA + mf * 16;
        aAddr[mf] = r * 64;
        rxA[mf] = (r >> 1) & 3;
    }
#pragma unroll
    for (int nf2 = 0; nf2 < 2; nf2++) {
        int r = rB + nf2 * 16;
        bAddr[nf2] = r * 64;
        rxB[nf2] = (r >> 1) & 3;
    }

    issue_stage(sb, 0, mg, nt, tid);
    issue_stage(sb, 1, mg, nt, tid);

#pragma unroll 1
    for (int c = 0; c < NCH; c++) {
        if (c < NCH - 2)
            asm volatile("cp.async.wait_group 1;" ::: "memory");
        else
            asm volatile("cp.async.wait_group 0;" ::: "memory");
        __syncthreads();
        if (c + 2 < NCH) issue_stage(sb, c + 2, mg, nt, tid);

        const uint32_t st = sb + (c % NSTAGE) * STAGE_BYTES;
#pragma unroll
        for (int kh = 0; kh < 2; kh++) {
            uint32_t Ah[4][4], Al[4][4], Bh[2][4], Bl[2][4];
#pragma unroll
            for (int mf = 0; mf < 4; mf++)
                ldsm4(Ah[mf], st + OFF_AH + aAddr[mf] + (((kh * 2 + a_c4) ^ rxA[mf]) << 4));
#pragma unroll
            for (int nf2 = 0; nf2 < 2; nf2++)
                ldsm4(Bh[nf2], st + OFF_BH + bAddr[nf2] + (((kh * 2 + b_c4) ^ rxB[nf2]) << 4));
#pragma unroll
            for (int mf = 0; mf < 4; mf++)
#pragma unroll
                for (int nf = 0; nf < 4; nf++)
                    mma16816(acc[mf][nf], Ah[mf], &Bh[nf >> 1][(nf & 1) * 2]);
#pragma unroll
            for (int nf2 = 0; nf2 < 2; nf2++)
                ldsm4(Bl[nf2], st + OFF_BL + bAddr[nf2] + (((kh * 2 + b_c4) ^ rxB[nf2]) << 4));
#pragma unroll
            for (int mf = 0; mf < 4; mf++)
#pragma unroll
                for (int nf = 0; nf < 4; nf++)
                    mma16816(acc[mf][nf], Ah[mf], &Bl[nf >> 1][(nf & 1) * 2]);
#pragma unroll
            for (int mf = 0; mf < 4; mf++)
                ldsm4(Al[mf], st + OFF_AL + aAddr[mf] + (((kh * 2 + a_c4) ^ rxA[mf]) << 4));
#pragma unroll
            for (int mf = 0; mf < 4; mf++)
#pragma unroll
                for (int nf = 0; nf < 4; nf++)
                    mma16816(acc[mf][nf], Al[mf], &Bh[nf >> 1][(nf & 1) * 2]);
        }
    }

    const int mrow_t = wm + (lane >> 2);           // row within tile
    const int ncol_t = wn + (lane & 3) * 2;        // col within tile

    if (MODE == 0) {
        // Sample pass: store sims to g_sample
#pragma unroll
        for (int mf = 0; mf < 4; mf++) {
#pragma unroll
            for (int nf = 0; nf < 4; nf++) {
                int n = nt * 128 + ncol_t + nf * 8;
                size_t r0 = (size_t)(mg * 128 + mrow_t + mf * 16);
                *(float2*)(g_sample + r0 * SAMPLE_COLS + n) =
                    make_float2(acc[mf][nf][0], acc[mf][nf][1]);
                *(float2*)(g_sample + (r0 + 8) * SAMPLE_COLS + n) =
                    make_float2(acc[mf][nf][2], acc[mf][nf][3]);
            }
        }
    } else {
        // Filter pass: stage tile in smem (register-light), then scan & push
        float* epi = (float*)dsm;
        __syncthreads();   // pipeline smem is dead; safe to reuse
#pragma unroll
        for (int mf = 0; mf < 4; mf++) {
#pragma unroll
            for (int nf = 0; nf < 4; nf++) {
                int col = ncol_t + nf * 8;
                int r0 = mrow_t + mf * 16;
                *(float2*)(epi + r0 * EPI_STRIDE + col) =
                    make_float2(acc[mf][nf][0], acc[mf][nf][1]);
                *(float2*)(epi + (r0 + 8) * EPI_STRIDE + col) =
                    make_float2(acc[mf][nf][2], acc[mf][nf][3]);
            }
        }
        __syncthreads();

        // Each thread scans half a row (64 floats) of the staged tile
        const int row = tid >> 1;
        const int cbase = (tid & 1) * 64;
        const int grow = mg * 128 + row;
        const float th = g_thresh[grow];
        const float* rp = epi + row * EPI_STRIDE + cbase;
        const int nbase = nt * 128 + cbase;
        const int nvalid = N_FEATS - nbase;   // may exceed 64; may be <= 0
#pragma unroll 4
        for (int i4 = 0; i4 < 16; i4++) {
            float4 v = *(const float4*)(rp + i4 * 4);
            if (v.x >= th || v.y >= th || v.z >= th || v.w >= th) {
                int j = i4 * 4;
#pragma unroll
                for (int q = 0; q < 4; q++) {
                    float val = (q == 0) ? v.x : (q == 1) ? v.y : (q == 2) ? v.z : v.w;
                    if (val >= th && j + q < nvalid) {
                        int p = atomicAdd(&g_ccnt[grow], 1);
                        if (p < CAP) {
                            g_cvv[(size_t)grow * CAP + p] = val;
                            g_cii[(size_t)grow * CAP + p] = nbase + j + q;
                        }
                    }
                }
            }
        }
    }
}

// ---------------------------------------------------------------------------
// Top-10 machinery (tie-break: lower index, matching stable argsort)
// ---------------------------------------------------------------------------
static __device__ __forceinline__ bool better(float v, int j, float v2, int j2) {
    return v > v2 || (v == v2 && j < j2);
}
static __device__ __forceinline__ void insert10(float (&tv)[TOPK], int (&ti)[TOPK],
                                                float v, int j) {
    if (!better(v, j, tv[TOPK - 1], ti[TOPK - 1])) return;
    bool b[TOPK];
#pragma unroll
    for (int p = 0; p < TOPK; p++) b[p] = better(v, j, tv[p], ti[p]);
#pragma unroll
    for (int p = TOPK - 1; p >= 1; p--) {
        if (b[p]) {
            if (b[p - 1]) { tv[p] = tv[p - 1]; ti[p] = ti[p - 1]; }
            else          { tv[p] = v;         ti[p] = j;         }
        }
    }
    if (b[0]) { tv[0] = v; ti[0] = j; }
}

#define TK_THREADS 256

static __device__ __forceinline__ void block_merge10(float (&tv)[TOPK], int (&ti)[TOPK],
                                                     float* sv, int* si, float* sv2,
                                                     int* si2, int tid) {
#pragma unroll
    for (int p = 0; p < TOPK; p++) { sv[tid * TOPK + p] = tv[p]; si[tid * TOPK + p] = ti[p]; }
    __syncthreads();
    if (tid < 32) {
#pragma unroll
        for (int p = 0; p < TOPK; p++) { tv[p] = -__int_as_float(0x7f800000); ti[p] = 0x7fffffff; }
        for (int c = tid * 80; c < (tid + 1) * 80; c++)
            insert10(tv, ti, sv[c], si[c]);
#pragma unroll
        for (int p = 0; p < TOPK; p++) { sv2[tid * TOPK + p] = tv[p]; si2[tid * TOPK + p] = ti[p]; }
    }
    __syncthreads();
    if (tid == 0) {
#pragma unroll
        for (int p = 0; p < TOPK; p++) { tv[p] = -__int_as_float(0x7f800000); ti[p] = 0x7fffffff; }
        for (int c = 0; c < 32 * TOPK; c++)
            insert10(tv, ti, sv2[c], si2[c]);
    }
}

__global__ void __launch_bounds__(TK_THREADS) thresh_kernel() {
    const int row = blockIdx.x;
    const float* s = g_sample + (size_t)row * SAMPLE_COLS;
    const int tid = threadIdx.x;
    __shared__ float sv[TK_THREADS * TOPK];
    __shared__ int   si[TK_THREADS * TOPK];
    __shared__ float sv2[32 * TOPK];
    __shared__ int   si2[32 * TOPK];

    float tv[TOPK]; int ti[TOPK];
#pragma unroll
    for (int p = 0; p < TOPK; p++) { tv[p] = -__int_as_float(0x7f800000); ti[p] = 0x7fffffff; }
    for (int j = tid; j < SAMPLE_COLS; j += TK_THREADS)
        insert10(tv, ti, s[j], j);
    block_merge10(tv, ti, sv, si, sv2, si2, tid);
    if (tid == 0) g_thresh[row] = tv[TOPK - 1];
}

__global__ void __launch_bounds__(TK_THREADS) select_kernel() {
    const int row = blockIdx.x;
    const int tid = threadIdx.x;
    const int cnt = g_ccnt[row];
    if (cnt > CAP) return;

    __shared__ float sv[TK_THREADS * TOPK];
    __shared__ int   si[TK_THREADS * TOPK];
    __shared__ float sv2[32 * TOPK];
    __shared__ int   si2[32 * TOPK];

    float tv[TOPK]; int ti[TOPK];
#pragma unroll
    for (int p = 0; p < TOPK; p++) { tv[p] = -__int_as_float(0x7f800000); ti[p] = 0x7fffffff; }
    const float* cv = g_cvv + (size_t)row * CAP;
    const int*   ci = g_cii + (size_t)row * CAP;
    for (int c = tid; c < cnt; c += TK_THREADS)
        insert10(tv, ti, cv[c], ci[c]);
    block_merge10(tv, ti, sv, si, sv2, si2, tid);
    if (tid == 0) {
#pragma unroll
        for (int p = 0; p < TOPK; p++) g_topk[row * TOPK + p] = ti[p];
    }
}

// Fallback: brute-force exact fp32 top-10 for overflow rows (normally a no-op)
__global__ void __launch_bounds__(TK_THREADS) fallback_kernel(const float* __restrict__ yp,
                                                              const float* __restrict__ feats) {
    const int row = blockIdx.x;
    if (g_ccnt[row] <= CAP) return;
    const int tid = threadIdx.x;

    __shared__ float4 a4[D_DIM / 4];
    __shared__ float sv[TK_THREADS * TOPK];
    __shared__ int   si[TK_THREADS * TOPK];
    __shared__ float sv2[32 * TOPK];
    __shared__ int   si2[32 * TOPK];

    if (tid < D_DIM / 4) a4[tid] = ((const float4*)(yp + (size_t)row * D_DIM))[tid];
    __syncthreads();

    float tv[TOPK]; int ti[TOPK];
#pragma unroll
    for (int p = 0; p < TOPK; p++) { tv[p] = -__int_as_float(0x7f800000); ti[p] = 0x7fffffff; }
    for (int col = tid; col < N_FEATS; col += TK_THREADS) {
        const float4* f4 = (const float4*)(feats + (size_t)col * D_DIM);
        float s = 0.f;
#pragma unroll 8
        for (int q = 0; q < D_DIM / 4; q++) {
            float4 b = f4[q], a = a4[q];
            s += a.x * b.x + a.y * b.y + a.z * b.z + a.w * b.w;
        }
        insert10(tv, ti, s, col);
    }
    block_merge10(tv, ti, sv, si, sv2, si2, tid);
    if (tid == 0) {
#pragma unroll
        for (int p = 0; p < TOPK; p++) g_topk[row * TOPK + p] = ti[p];
    }
}

// ---------------------------------------------------------------------------
__global__ void zero_kernel(float4* __restrict__ out, int n4) {
    int i = blockIdx.x * blockDim.x + threadIdx.x;
    if (i < n4) out[i] = make_float4(0.f, 0.f, 0.f, 0.f);
}
__global__ void scatter_kernel(const int* __restrict__ y, float* __restrict__ out) {
    int row = blockIdx.x;
    int t = threadIdx.x;
    if (t < TOPK) {
        int idx = g_topk[row * TOPK + t];
        int cls = y[idx];
        out[(size_t)row * C_CLS + cls] = 1.0f;
    }
}

// ---------------------------------------------------------------------------
extern "C" void kernel_launch(void* const* d_in, const int* in_sizes, int n_in,
                              void* d_out, int out_size) {
    const float* y_pred = (const float*)d_in[0];
    const float* feats  = (const float*)d_in[1];
    const int*   y      = (const int*)d_in[2];
    float* out = (float*)d_out;

    static __nv_bfloat16 *p_fhi = nullptr, *p_flo = nullptr, *p_ahi = nullptr, *p_alo = nullptr;
    if (!p_fhi) {
        cudaGetSymbolAddress((void**)&p_fhi, g_fhi);
        cudaGetSymbolAddress((void**)&p_flo, g_flo);
        cudaGetSymbolAddress((void**)&p_ahi, g_ahi);
        cudaGetSymbolAddress((void**)&p_alo, g_alo);
        cudaFuncSetAttribute(gemm_hmma<0>, cudaFuncAttributeMaxDynamicSharedMemorySize,
                             SMEM_TOTAL);
        cudaFuncSetAttribute(gemm_hmma<1>, cudaFuncAttributeMaxDynamicSharedMemorySize,
                             SMEM_TOTAL);
    }

    cvt_kernel<<<(N_FEATS * D_DIM / 8 + 255) / 256, 256>>>(feats, p_fhi, p_flo,
                                                           N_FEATS * D_DIM / 8);
    cvt_kernel<<<(B_ROWS * D_DIM / 8 + 255) / 256, 256>>>(y_pred, p_ahi, p_alo,
                                                          B_ROWS * D_DIM / 8);
    zero_cnt_kernel<<<1, 256>>>();

    gemm_hmma<0><<<dim3(4, SAMPLE_NT), 256, SMEM_TOTAL>>>();
    thresh_kernel<<<B_ROWS, TK_THREADS>>>();

    gemm_hmma<1><<<dim3(4, (N_FEATS + 127) / 128), 256, SMEM_TOTAL>>>();

    select_kernel<<<B_ROWS, TK_THREADS>>>();
    fallback_kernel<<<B_ROWS, TK_THREADS>>>(y_pred, feats);

    int n4 = out_size / 4;
    zero_kernel<<<(n4 + 255) / 256, 256>>>((float4*)out, n4);
    scatter_kernel<<<B_ROWS, 32>>>(y, out);
}

// round 9
// speedup vs baseline: 1.1330x; 1.0969x over previous
#include <cuda_runtime.h>
#include <cuda_bf16.h>
#include <cstdint>

#define N_FEATS 100000
#define B_ROWS  512
#define D_DIM   512
#define C_CLS   1854
#define TOPK    10

#define KC      32
#define NCH     (D_DIM / KC)        // 16
#define NSTAGE  4
#define STAGE_BYTES 16384           // A_hi 8K + B_hi 8K
#define SMEM_TOTAL 69632            // max(4 stages = 64K, epilogue 128*132*4 = 66K)
#define OFF_AH 0
#define OFF_BH 8192
#define EPI_STRIDE 132

#define SAMPLE_NT 16
#define SAMPLE_COLS (SAMPLE_NT * 128)
#define CAP 4096
#define MARGIN 0.2f                 // > 2 * 2^-8 * ||a||*||b|| hard bf16-error bound

__device__ __nv_bfloat16 g_fhi[(size_t)N_FEATS * D_DIM];   // 102.4 MB
__device__ __nv_bfloat16 g_ahi[B_ROWS * D_DIM];
__device__ float g_sample[(size_t)B_ROWS * SAMPLE_COLS];   // 4 MB
__device__ float g_thresh[B_ROWS];                         // t_sample10 - MARGIN
__device__ int   g_ccnt[B_ROWS];
__device__ int   g_cii[(size_t)B_ROWS * CAP];              // 8 MB
__device__ int   g_topk[B_ROWS * TOPK];

static __device__ __forceinline__ uint32_t smem_u32(const void* p) {
    uint32_t a;
    asm("{ .reg .u64 t; cvta.to.shared.u64 t, %1; cvt.u32.u64 %0, t; }" : "=r"(a) : "l"(p));
    return a;
}
static __device__ __forceinline__ void ldsm4(uint32_t (&r)[4], uint32_t addr) {
    asm volatile("ldmatrix.sync.aligned.m8n8.x4.shared.b16 {%0,%1,%2,%3}, [%4];"
                 : "=r"(r[0]), "=r"(r[1]), "=r"(r[2]), "=r"(r[3]) : "r"(addr));
}
static __device__ __forceinline__ void mma16816(float (&d)[4], const uint32_t (&a)[4],
                                                const uint32_t* b) {
    asm volatile(
        "mma.sync.aligned.m16n8k16.row.col.f32.bf16.bf16.f32 "
        "{%0,%1,%2,%3}, {%4,%5,%6,%7}, {%8,%9}, {%0,%1,%2,%3};"
        : "+f"(d[0]), "+f"(d[1]), "+f"(d[2]), "+f"(d[3])
        : "r"(a[0]), "r"(a[1]), "r"(a[2]), "r"(a[3]), "r"(b[0]), "r"(b[1]));
}
static __device__ __forceinline__ void cp16(uint32_t dst, const void* src, uint32_t sz) {
    asm volatile("cp.async.cg.shared.global [%0], [%1], 16, %2;"
                 :: "r"(dst), "l"(src), "r"(sz) : "memory");
}

// ---------------------------------------------------------------------------
// Pre-convert: fp32 -> bf16 hi only
// ---------------------------------------------------------------------------
__global__ void cvt_hi_kernel(const float* __restrict__ src, __nv_bfloat16* __restrict__ hi,
                              int n8) {
    int i = blockIdx.x * blockDim.x + threadIdx.x;
    if (i >= n8) return;
    float4 v0 = ((const float4*)src)[i * 2];
    float4 v1 = ((const float4*)src)[i * 2 + 1];
    __nv_bfloat162 h0 = __floats2bfloat162_rn(v0.x, v0.y);
    __nv_bfloat162 h1 = __floats2bfloat162_rn(v0.z, v0.w);
    __nv_bfloat162 h2 = __floats2bfloat162_rn(v1.x, v1.y);
    __nv_bfloat162 h3 = __floats2bfloat162_rn(v1.z, v1.w);
    ((uint4*)hi)[i] = make_uint4(*(uint32_t*)&h0, *(uint32_t*)&h1,
                                 *(uint32_t*)&h2, *(uint32_t*)&h3);
}

__global__ void zero_cnt_kernel() {
    ((int2*)g_ccnt)[threadIdx.x] = make_int2(0, 0);
}

// ---------------------------------------------------------------------------
// GEMM: cp.async 4-stage, single-pass bf16 HMMA
// MODE 0: store sims to g_sample   MODE 1: smem-staged filter, push indices
// ---------------------------------------------------------------------------
extern __shared__ char dsm[];

static __device__ __forceinline__ void issue_stage(uint32_t sbase, int c, int mg, int nt,
                                                   int tid) {
    const uint32_t stage = sbase + (c % NSTAGE) * STAGE_BYTES;
#pragma unroll
    for (int j = 0; j < 4; j++) {
        int id = tid + j * 256;     // 0..1023
        int mat = id >> 9;          // 0:Ah 1:Bh
        int rem = id & 511;
        int row = rem >> 2;
        int cc = rem & 3;
        uint32_t dst = stage + mat * 8192 + row * 64 + ((cc ^ ((row >> 1) & 3)) << 4);
        uint32_t sz = 16;
        const __nv_bfloat16* src;
        if (mat == 0) {
            src = g_ahi + (size_t)(mg * 128 + row) * D_DIM + c * KC + cc * 8;
        } else {
            int n = nt * 128 + row;
            if (n >= N_FEATS) { sz = 0; n = 0; }
            src = g_fhi + (size_t)n * D_DIM + c * KC + cc * 8;
        }
        cp16(dst, src, sz);
    }
    asm volatile("cp.async.commit_group;" ::: "memory");
}

template <int MODE>
__global__ void __launch_bounds__(256, 2) gemm_hmma(void) {
    const int mg = blockIdx.x;
    const int nt = blockIdx.y;
    const int tid = threadIdx.x;
    const int lane = tid & 31, w = tid >> 5;
    const int wm = (w >> 2) * 64;
    const int wn = (w & 3) * 32;
    const uint32_t sb = smem_u32(dsm);

    float acc[4][4][4];
#pragma unroll
    for (int i = 0; i < 4; i++)
#pragma unroll
        for (int j = 0; j < 4; j++)
#pragma unroll
            for (int q = 0; q < 4; q++) acc[i][j][q] = 0.f;

    const int rA = wm + ((lane >> 3) & 1) * 8 + (lane & 7);
    const int a_c4 = lane >> 4;
    const int rB = wn + ((lane >> 4) & 1) * 8 + (lane & 7);
    const int b_c4 = (lane >> 3) & 1;

    uint32_t aAddr[4], bAddr[2];
    int rxA[4], rxB[2];
#pragma unroll
    for (int mf = 0; mf < 4; mf++) {
        int r = rA + mf * 16;
        aAddr[mf] = r * 64;
        rxA[mf] = (r >> 1) & 3;
    }
#pragma unroll
    for (int nf2 = 0; nf2 < 2; nf2++) {
        int r = rB + nf2 * 16;
        bAddr[nf2] = r * 64;
        rxB[nf2] = (r >> 1) & 3;
    }

    issue_stage(sb, 0, mg, nt, tid);
    issue_stage(sb, 1, mg, nt, tid);
    issue_stage(sb, 2, mg, nt, tid);

#pragma unroll 1
    for (int c = 0; c < NCH; c++) {
        if (c <= NCH - 3)
            asm volatile("cp.async.wait_group 2;" ::: "memory");
        else if (c == NCH - 2)
            asm volatile("cp.async.wait_group 1;" ::: "memory");
        else
            asm volatile("cp.async.wait_group 0;" ::: "memory");
        __syncthreads();
        if (c + 3 < NCH) issue_stage(sb, c + 3, mg, nt, tid);

        const uint32_t st = sb + (c % NSTAGE) * STAGE_BYTES;
#pragma unroll
        for (int kh = 0; kh < 2; kh++) {
            uint32_t Ah[4][4], Bh[2][4];
#pragma unroll
            for (int mf = 0; mf < 4; mf++)
                ldsm4(Ah[mf], st + OFF_AH + aAddr[mf] + (((kh * 2 + a_c4) ^ rxA[mf]) << 4));
#pragma unroll
            for (int nf2 = 0; nf2 < 2; nf2++)
                ldsm4(Bh[nf2], st + OFF_BH + bAddr[nf2] + (((kh * 2 + b_c4) ^ rxB[nf2]) << 4));
#pragma unroll
            for (int mf = 0; mf < 4; mf++)
#pragma unroll
                for (int nf = 0; nf < 4; nf++)
                    mma16816(acc[mf][nf], Ah[mf], &Bh[nf >> 1][(nf & 1) * 2]);
        }
    }

    const int mrow_t = wm + (lane >> 2);
    const int ncol_t = wn + (lane & 3) * 2;

    if (MODE == 0) {
#pragma unroll
        for (int mf = 0; mf < 4; mf++) {
#pragma unroll
            for (int nf = 0; nf < 4; nf++) {
                int n = nt * 128 + ncol_t + nf * 8;
                size_t r0 = (size_t)(mg * 128 + mrow_t + mf * 16);
                *(float2*)(g_sample + r0 * SAMPLE_COLS + n) =
                    make_float2(acc[mf][nf][0], acc[mf][nf][1]);
                *(float2*)(g_sample + (r0 + 8) * SAMPLE_COLS + n) =
                    make_float2(acc[mf][nf][2], acc[mf][nf][3]);
            }
        }
    } else {
        float* epi = (float*)dsm;
        __syncthreads();
#pragma unroll
        for (int mf = 0; mf < 4; mf++) {
#pragma unroll
            for (int nf = 0; nf < 4; nf++) {
                int col = ncol_t + nf * 8;
                int r0 = mrow_t + mf * 16;
                *(float2*)(epi + r0 * EPI_STRIDE + col) =
                    make_float2(acc[mf][nf][0], acc[mf][nf][1]);
                *(float2*)(epi + (r0 + 8) * EPI_STRIDE + col) =
                    make_float2(acc[mf][nf][2], acc[mf][nf][3]);
            }
        }
        __syncthreads();

        const int row = tid >> 1;
        const int cbase = (tid & 1) * 64;
        const int grow = mg * 128 + row;
        const float th = g_thresh[grow];   // already includes -MARGIN
        const float* rp = epi + row * EPI_STRIDE + cbase;
        const int nbase = nt * 128 + cbase;
        const int nvalid = N_FEATS - nbase;
#pragma unroll 4
        for (int i4 = 0; i4 < 16; i4++) {
            float4 v = *(const float4*)(rp + i4 * 4);
            if (v.x >= th || v.y >= th || v.z >= th || v.w >= th) {
                int j = i4 * 4;
#pragma unroll
                for (int q = 0; q < 4; q++) {
                    float val = (q == 0) ? v.x : (q == 1) ? v.y : (q == 2) ? v.z : v.w;
                    if (val >= th && j + q < nvalid) {
                        int p = atomicAdd(&g_ccnt[grow], 1);
                        if (p < CAP) g_cii[(size_t)grow * CAP + p] = nbase + j + q;
                    }
                }
            }
        }
    }
}

// ---------------------------------------------------------------------------
// Top-10 machinery (tie-break: lower index, matching stable argsort)
// ---------------------------------------------------------------------------
static __device__ __forceinline__ bool better(float v, int j, float v2, int j2) {
    return v > v2 || (v == v2 && j < j2);
}
static __device__ __forceinline__ void insert10(float (&tv)[TOPK], int (&ti)[TOPK],
                                                float v, int j) {
    if (!better(v, j, tv[TOPK - 1], ti[TOPK - 1])) return;
    bool b[TOPK];
#pragma unroll
    for (int p = 0; p < TOPK; p++) b[p] = better(v, j, tv[p], ti[p]);
#pragma unroll
    for (int p = TOPK - 1; p >= 1; p--) {
        if (b[p]) {
            if (b[p - 1]) { tv[p] = tv[p - 1]; ti[p] = ti[p - 1]; }
            else          { tv[p] = v;         ti[p] = j;         }
        }
    }
    if (b[0]) { tv[0] = v; ti[0] = j; }
}

#define TK_THREADS 256

static __device__ __forceinline__ void block_merge10(float (&tv)[TOPK], int (&ti)[TOPK],
                                                     float* sv, int* si, float* sv2,
                                                     int* si2, int tid) {
#pragma unroll
    for (int p = 0; p < TOPK; p++) { sv[tid * TOPK + p] = tv[p]; si[tid * TOPK + p] = ti[p]; }
    __syncthreads();
    if (tid < 32) {
#pragma unroll
        for (int p = 0; p < TOPK; p++) { tv[p] = -__int_as_float(0x7f800000); ti[p] = 0x7fffffff; }
        for (int c = tid * 80; c < (tid + 1) * 80; c++)
            insert10(tv, ti, sv[c], si[c]);
#pragma unroll
        for (int p = 0; p < TOPK; p++) { sv2[tid * TOPK + p] = tv[p]; si2[tid * TOPK + p] = ti[p]; }
    }
    __syncthreads();
    if (tid == 0) {
#pragma unroll
        for (int p = 0; p < TOPK; p++) { tv[p] = -__int_as_float(0x7f800000); ti[p] = 0x7fffffff; }
        for (int c = 0; c < 32 * TOPK; c++)
            insert10(tv, ti, sv2[c], si2[c]);
    }
}

// Threshold = (10th largest bf16 sim of sample) - MARGIN
__global__ void __launch_bounds__(TK_THREADS) thresh_kernel() {
    const int row = blockIdx.x;
    const float* s = g_sample + (size_t)row * SAMPLE_COLS;
    const int tid = threadIdx.x;
    __shared__ float sv[TK_THREADS * TOPK];
    __shared__ int   si[TK_THREADS * TOPK];
    __shared__ float sv2[32 * TOPK];
    __shared__ int   si2[32 * TOPK];

    float tv[TOPK]; int ti[TOPK];
#pragma unroll
    for (int p = 0; p < TOPK; p++) { tv[p] = -__int_as_float(0x7f800000); ti[p] = 0x7fffffff; }
    for (int j = tid; j < SAMPLE_COLS; j += TK_THREADS)
        insert10(tv, ti, s[j], j);
    block_merge10(tv, ti, sv, si, sv2, si2, tid);
    if (tid == 0) g_thresh[row] = tv[TOPK - 1] - MARGIN;
}

// Rescore candidates exactly in fp32, then exact top-10
__global__ void __launch_bounds__(TK_THREADS) rescore_select(const float* __restrict__ yp,
                                                             const float* __restrict__ feats) {
    const int row = blockIdx.x;
    const int tid = threadIdx.x;
    const int lane = tid & 31, w = tid >> 5;
    const int cnt = g_ccnt[row];
    if (cnt > CAP) return;   // fallback kernel handles

    __shared__ float4 a4s[D_DIM / 4];
    __shared__ float  cvs[CAP];           // 16 KB
    __shared__ float sv[TK_THREADS * TOPK];
    __shared__ int   si[TK_THREADS * TOPK];
    __shared__ float sv2[32 * TOPK];
    __shared__ int   si2[32 * TOPK];

    if (tid < D_DIM / 4) a4s[tid] = ((const float4*)(yp + (size_t)row * D_DIM))[tid];
    __syncthreads();

    const int* ci = g_cii + (size_t)row * CAP;
    for (int c = w; c < cnt; c += 8) {
        int idx = ci[c];
        const float4* f4 = (const float4*)(feats + (size_t)idx * D_DIM);
        float s = 0.f;
#pragma unroll
        for (int i = 0; i < 4; i++) {
            float4 b = f4[i * 32 + lane];
            float4 a = a4s[i * 32 + lane];
            s += a.x * b.x + a.y * b.y + a.z * b.z + a.w * b.w;
        }
#pragma unroll
        for (int o = 16; o; o >>= 1) s += __shfl_xor_sync(0xffffffffu, s, o);
        if (lane == 0) cvs[c] = s;
    }
    __syncthreads();

    float tv[TOPK]; int ti[TOPK];
#pragma unroll
    for (int p = 0; p < TOPK; p++) { tv[p] = -__int_as_float(0x7f800000); ti[p] = 0x7fffffff; }
    for (int c = tid; c < cnt; c += TK_THREADS)
        insert10(tv, ti, cvs[c], ci[c]);
    block_merge10(tv, ti, sv, si, sv2, si2, tid);
    if (tid == 0) {
#pragma unroll
        for (int p = 0; p < TOPK; p++) g_topk[row * TOPK + p] = ti[p];
    }
}

// Fallback: brute-force exact fp32 top-10 for overflow rows (normally a no-op)
__global__ void __launch_bounds__(TK_THREADS) fallback_kernel(const float* __restrict__ yp,
                                                              const float* __restrict__ feats) {
    const int row = blockIdx.x;
    if (g_ccnt[row] <= CAP) return;
    const int tid = threadIdx.x;

    __shared__ float4 a4[D_DIM / 4];
    __shared__ float sv[TK_THREADS * TOPK];
    __shared__ int   si[TK_THREADS * TOPK];
    __shared__ float sv2[32 * TOPK];
    __shared__ int   si2[32 * TOPK];

    if (tid < D_DIM / 4) a4[tid] = ((const float4*)(yp + (size_t)row * D_DIM))[tid];
    __syncthreads();

    float tv[TOPK]; int ti[TOPK];
#pragma unroll
    for (int p = 0; p < TOPK; p++) { tv[p] = -__int_as_float(0x7f800000); ti[p] = 0x7fffffff; }
    for (int col = tid; col < N_FEATS; col += TK_THREADS) {
        const float4* f4 = (const float4*)(feats + (size_t)col * D_DIM);
        float s = 0.f;
#pragma unroll 8
        for (int q = 0; q < D_DIM / 4; q++) {
            float4 b = f4[q], a = a4[q];
            s += a.x * b.x + a.y * b.y + a.z * b.z + a.w * b.w;
        }
        insert10(tv, ti, s, col);
    }
    block_merge10(tv, ti, sv, si, sv2, si2, tid);
    if (tid == 0) {
#pragma unroll
        for (int p = 0; p < TOPK; p++) g_topk[row * TOPK + p] = ti[p];
    }
}

// ---------------------------------------------------------------------------
__global__ void zero_kernel(float4* __restrict__ out, int n4) {
    int i = blockIdx.x * blockDim.x + threadIdx.x;
    if (i < n4) out[i] = make_float4(0.f, 0.f, 0.f, 0.f);
}
__global__ void scatter_kernel(const int* __restrict__ y, float* __restrict__ out) {
    int row = blockIdx.x;
    int t = threadIdx.x;
    if (t < TOPK) {
        int idx = g_topk[row * TOPK + t];
        int cls = y[idx];
        out[(size_t)row * C_CLS + cls] = 1.0f;
    }
}

// ---------------------------------------------------------------------------
extern "C" void kernel_launch(void* const* d_in, const int* in_sizes, int n_in,
                              void* d_out, int out_size) {
    const float* y_pred = (const float*)d_in[0];
    const float* feats  = (const float*)d_in[1];
    const int*   y      = (const int*)d_in[2];
    float* out = (float*)d_out;

    static __nv_bfloat16 *p_fhi = nullptr, *p_ahi = nullptr;
    if (!p_fhi) {
        cudaGetSymbolAddress((void**)&p_fhi, g_fhi);
        cudaGetSymbolAddress((void**)&p_ahi, g_ahi);
        cudaFuncSetAttribute(gemm_hmma<0>, cudaFuncAttributeMaxDynamicSharedMemorySize,
                             SMEM_TOTAL);
        cudaFuncSetAttribute(gemm_hmma<1>, cudaFuncAttributeMaxDynamicSharedMemorySize,
                             SMEM_TOTAL);
    }

    cvt_hi_kernel<<<(N_FEATS * D_DIM / 8 + 255) / 256, 256>>>(feats, p_fhi,
                                                              N_FEATS * D_DIM / 8);
    cvt_hi_kernel<<<(B_ROWS * D_DIM / 8 + 255) / 256, 256>>>(y_pred, p_ahi,
                                                             B_ROWS * D_DIM / 8);
    zero_cnt_kernel<<<1, 256>>>();

    gemm_hmma<0><<<dim3(4, SAMPLE_NT), 256, SMEM_TOTAL>>>();
    thresh_kernel<<<B_ROWS, TK_THREADS>>>();

    gemm_hmma<1><<<dim3(4, (N_FEATS + 127) / 128), 256, SMEM_TOTAL>>>();

    rescore_select<<<B_ROWS, TK_THREADS>>>(y_pred, feats);
    fallback_kernel<<<B_ROWS, TK_THREADS>>>(y_pred, feats);

    int n4 = out_size / 4;
    zero_kernel<<<(n4 + 255) / 256, 256>>>((float4*)out, n4);
    scatter_kernel<<<B_ROWS, 32>>>(y, out);
}